// round 5
// baseline (speedup 1.0000x reference)
#include <cuda_runtime.h>
#include <cuda_fp16.h>
#include <cstdint>

#define NLAYERS 25
#define KOUT 50
#define FW 1266
#define ROWS 64
#define THREADS 512
#define MAXKS 76
#define NT 7
#define RSE 1272                         // fp16 elems/row (2544B, 16B-aligned)
#define A_BYTES (ROWS * RSE * 2)         // 162816
#define KSB 3584                         // bytes per ks block: 7 nt * 32 lanes * 16B
#define CK 4                             // ks per chunk
#define NBUF 3
#define CHUNK_B (CK * KSB)               // 14336
#define OPS (CK * 224)                   // 896 cp16 ops per chunk
#define WOFF A_BYTES                     // 162816
#define SCOFF (WOFF + NBUF * CHUNK_B)    // 205824
#define MBOFF (SCOFF + 16384)            // 222208
#define SMEM_TOTAL (MBOFF + 64)          // 222272

// W fragments: [layer][ks(76)][nt(7)][lane(32)][word(4)]; word = {bhi_r0,bhi_r1,blo_r0,blo_r1}
#define WFRAG_WORDS (NLAYERS * MAXKS * NT * 32 * 4)   // 1,702,400 (6.81 MB)
__device__ uint32_t g_wfrag[WFRAG_WORDS];

__device__ __forceinline__ uint32_t packh2(__half a, __half b) {
    return (uint32_t)__half_as_ushort(a) | ((uint32_t)__half_as_ushort(b) << 16);
}

// ---- prekernel: fp32 W -> fragment-ordered fp16 hi/lo quads ----
__global__ void stage_w_kernel(const float* __restrict__ Ws) {
    int i = blockIdx.x * blockDim.x + threadIdx.x;
    if (i >= WFRAG_WORDS) return;
    int w = i;
    int word = w & 3;  w >>= 2;
    int ln   = w & 31; w >>= 5;
    int nt   = w % NT; w /= NT;
    int ks   = w % MAXKS;
    int layer = w / MAXKS;
    int plane = word >> 1;
    int reg   = word & 1;
    int n = nt * 8 + (ln >> 2);
    int k = ks * 16 + ((ln & 3) << 1) + reg * 8;
    float w0 = 0.f, w1 = 0.f;
    if (n < KOUT) {
        const float* p = Ws + ((size_t)layer * KOUT + n) * FW + k;
        w0 = p[0]; w1 = p[1];
    }
    uint32_t v;
    if (plane == 0) {
        v = packh2(__float2half_rn(w0), __float2half_rn(w1));
    } else {
        __half h0 = __float2half_rn(w0), h1 = __float2half_rn(w1);
        v = packh2(__float2half_rn(w0 - __half2float(h0)),
                   __float2half_rn(w1 - __half2float(h1)));
    }
    g_wfrag[i] = v;
}

#define MMA(d, a, b0_, b1_) \
    asm volatile("mma.sync.aligned.m16n8k16.row.col.f32.f16.f16.f32 " \
        "{%0,%1,%2,%3},{%4,%5,%6,%7},{%8,%9},{%0,%1,%2,%3};" \
        : "+f"(d[0]), "+f"(d[1]), "+f"(d[2]), "+f"(d[3]) \
        : "r"(a[0]), "r"(a[1]), "r"(a[2]), "r"(a[3]), "r"(b0_), "r"(b1_))

#define LDSM4(r, addr) \
    asm volatile("ldmatrix.sync.aligned.m8n8.x4.shared.b16 {%0,%1,%2,%3}, [%4];" \
        : "=r"(r[0]), "=r"(r[1]), "=r"(r[2]), "=r"(r[3]) : "r"(addr))

__device__ __forceinline__ void cp16(uint32_t dst, const void* src) {
    asm volatile("cp.async.cg.shared.global [%0], [%1], 16;" :: "r"(dst), "l"(src));
}

__device__ __forceinline__ void mbar_init(uint32_t addr, uint32_t count) {
    asm volatile("mbarrier.init.shared.b64 [%0], %1;" :: "r"(addr), "r"(count) : "memory");
}
__device__ __forceinline__ void mbar_arrive(uint32_t addr) {
    asm volatile("mbarrier.arrive.shared.b64 _, [%0];" :: "r"(addr) : "memory");
}
__device__ __forceinline__ void mbar_wait(uint32_t addr, uint32_t parity) {
    asm volatile(
        "{\n\t"
        ".reg .pred P;\n"
        "WL_%=:\n\t"
        "mbarrier.try_wait.parity.acquire.cta.shared::cta.b64 P, [%0], %1, 0x989680;\n\t"
        "@P bra WD_%=;\n\t"
        "bra WL_%=;\n"
        "WD_%=:\n\t"
        "}"
        :: "r"(addr), "r"(parity) : "memory");
}
__device__ __forceinline__ void cp_arrive_noinc(uint32_t addr) {
    asm volatile("cp.async.mbarrier.arrive.noinc.shared::cta.b64 [%0];"
                 :: "r"(addr) : "memory");
}

struct Prod { int pl, pks, pstage, pphase; };

__device__ __forceinline__ void produce(Prod& p, int tid, uint32_t wsm, uint32_t mb) {
    if (p.pl >= NLAYERS) return;
    const int nks = (31 + 50 * p.pl) >> 4;
    mbar_wait(mb + 32 + p.pstage * 8, (uint32_t)p.pphase);   // wait empty
    const uint32_t dstb = wsm + p.pstage * CHUNK_B;
    const char* srcb = (const char*)g_wfrag + (size_t)(p.pl * MAXKS + p.pks) * KSB;
    for (int i = tid; i < OPS; i += THREADS) {
        if (p.pks + i / 224 < nks)
            cp16(dstb + i * 16, srcb + (size_t)i * 16);
    }
    cp_arrive_noinc(mb + p.pstage * 8);                      // arrive full
    if (++p.pstage == NBUF) { p.pstage = 0; p.pphase ^= 1; }
    p.pks += CK;
    if (p.pks >= nks) { p.pl++; p.pks = 0; }
}

__global__ void __launch_bounds__(THREADS, 1) value_model_mma_kernel(
    const float* __restrict__ state,
    const float* __restrict__ bs,
    const float* __restrict__ Wout,
    const float* __restrict__ bout,
    float* __restrict__ out)
{
    extern __shared__ char smraw[];
    __half* A = (__half*)smraw;
    const uint32_t sm_u32 = (uint32_t)__cvta_generic_to_shared(smraw);
    const uint32_t wsm = sm_u32 + WOFF;
    const uint32_t mb  = sm_u32 + MBOFF;
    float4* scratch4 = (float4*)(smraw + SCOFF);

    const int tid  = threadIdx.x;
    const int lane = tid & 31;
    const int wid  = tid >> 5;
    const int cta  = blockIdx.x;
    const int ksl  = wid >> 2;         // 0..3: ks-lane (ks % 4)
    const int m    = (wid >> 1) & 1;   // row-half
    const int ng   = wid & 1;          // n-group (tiles ng*4 ..)

    // ---- zero A plane ----
    {
        uint4 z = make_uint4(0u, 0u, 0u, 0u);
        uint4* p = (uint4*)smraw;
        for (int i = tid; i < A_BYTES / 16; i += THREADS) p[i] = z;
    }
    // ---- mbarrier init ----
    if (tid == 0) {
        for (int i = 0; i < NBUF; i++) {
            mbar_init(mb + i * 8, THREADS);      // full: 512 noinc arrives
            mbar_init(mb + 32 + i * 8, 16);      // empty: 16 warp arrives
        }
    }
    __syncthreads();

    // ---- initial state (64 x 16) ----
    for (int idx = tid; idx < ROWS * 16; idx += THREADS) {
        int r = idx >> 4, j = idx & 15;
        A[r * RSE + j] = __float2half_rn(state[(cta * ROWS + r) * 16 + j]);
    }
    __syncthreads();

    const uint32_t abase = sm_u32 + (uint32_t)((m * 32 + (lane & 15)) * RSE) * 2u
                                  + (uint32_t)(lane >> 4) * 16u;

    Prod prod = {0, 0, 0, 1};   // producer phase=1: first empty-wait passes
    int cstage = 0, cphase = 0; // consumer cursor

    // prime the ring (lookahead = NBUF-1 = 2 chunks)
    produce(prod, tid, wsm, mb);
    produce(prod, tid, wsm, mb);

    int width = 16;
    for (int l = 0; l < NLAYERS; l++) {
        const int nks = (width + 15) >> 4;
        const int nch = (nks + CK - 1) >> 2;

        float acc[2][4][4] = {};

        for (int c = 0; c < nch; c++) {
            produce(prod, tid, wsm, mb);
            mbar_wait(mb + cstage * 8, (uint32_t)cphase);    // wait full
            const int ks = c * CK + ksl;
            if (ks < nks) {
                const uint32_t* wk = (const uint32_t*)(smraw + WOFF
                                    + cstage * CHUNK_B + ksl * KSB);
                uint32_t a0[4], a1[4];
                const uint32_t ad = abase + (uint32_t)ks * 32u;
                LDSM4(a0, ad);
                LDSM4(a1, ad + 16u * RSE * 2u);
                #pragma unroll
                for (int t = 0; t < 4; t++) {
                    const int tile = ng * 4 + t;
                    if (tile < NT) {
                        const uint4 b = *(const uint4*)(wk + tile * 128 + lane * 4);
                        MMA(acc[0][t], a0, b.x, b.y);
                        MMA(acc[0][t], a0, b.z, b.w);
                        MMA(acc[1][t], a1, b.x, b.y);
                        MMA(acc[1][t], a1, b.z, b.w);
                    }
                }
            }
            if (lane == 0) mbar_arrive(mb + 32 + cstage * 8);   // arrive empty
            if (++cstage == NBUF) { cstage = 0; cphase ^= 1; }
        }

        // ---- epilogue: 3-wave ksl reduction through dedicated scratch ----
        #pragma unroll
        for (int q = 1; q <= 3; q++) {
            if (ksl == q) {
                #pragma unroll
                for (int mt = 0; mt < 2; mt++)
                    #pragma unroll
                    for (int t = 0; t < 4; t++)
                        scratch4[(m * 2 + ng) * 256 + (mt * 4 + t) * 32 + lane] =
                            make_float4(acc[mt][t][0], acc[mt][t][1],
                                        acc[mt][t][2], acc[mt][t][3]);
            }
            __syncthreads();
            if (ksl == 0) {
                #pragma unroll
                for (int mt = 0; mt < 2; mt++)
                    #pragma unroll
                    for (int t = 0; t < 4; t++) {
                        float4 v = scratch4[(m * 2 + ng) * 256 + (mt * 4 + t) * 32 + lane];
                        acc[mt][t][0] += v.x; acc[mt][t][1] += v.y;
                        acc[mt][t][2] += v.z; acc[mt][t][3] += v.w;
                    }
            }
            __syncthreads();
        }

        if (ksl == 0) {
            #pragma unroll
            for (int mt = 0; mt < 2; mt++)
                #pragma unroll
                for (int t = 0; t < 4; t++) {
                    const int tile = ng * 4 + t;
                    if (tile < NT) {
                        const int n0 = tile * 8 + ((lane & 3) << 1);
                        const int rbase = m * 32 + mt * 16 + (lane >> 2);
                        #pragma unroll
                        for (int half = 0; half < 2; half++) {
                            const int n = n0 + half;
                            if (n < KOUT) {
                                const float bz = bs[l * KOUT + n];
                                #pragma unroll
                                for (int rr = 0; rr < 2; rr++) {
                                    float y = acc[mt][t][rr * 2 + half] + bz;
                                    y = (y > 0.f) ? y : 0.01f * y;
                                    A[(rbase + rr * 8) * RSE + width + n] =
                                        __float2half_rn(y);
                                }
                            }
                        }
                    }
                }
        }
        width += KOUT;
        __syncthreads();
    }

    // ---- final projection: out[r] = x . Wout + bout ----
    #pragma unroll
    for (int t = 0; t < 4; t++) {
        const int r = wid * 4 + t;
        float s = 0.f;
        for (int j = lane; j < FW; j += 32)
            s += __half2float(A[r * RSE + j]) * Wout[j];
        #pragma unroll
        for (int o = 16; o; o >>= 1) s += __shfl_xor_sync(0xffffffffu, s, o);
        if (lane == 0) out[cta * ROWS + r] = s + bout[0];
    }
}

extern "C" void kernel_launch(void* const* d_in, const int* in_sizes, int n_in,
                              void* d_out, int out_size) {
    const float* state = (const float*)d_in[0];
    const float* Ws    = (const float*)d_in[1];
    const float* bs    = (const float*)d_in[2];
    const float* Wout  = (const float*)d_in[3];
    const float* bout  = (const float*)d_in[4];
    float* out = (float*)d_out;

    const int B = in_sizes[0] / 16;   // 32768

    stage_w_kernel<<<(WFRAG_WORDS + 255) / 256, 256>>>(Ws);

    cudaFuncSetAttribute(value_model_mma_kernel,
                         cudaFuncAttributeMaxDynamicSharedMemorySize, SMEM_TOTAL);
    value_model_mma_kernel<<<B / ROWS, THREADS, SMEM_TOTAL>>>(state, bs, Wout, bout, out);
}

// round 7
// speedup vs baseline: 1.2549x; 1.2549x over previous
#include <cuda_runtime.h>
#include <cuda_fp16.h>
#include <cstdint>

#define NLAYERS 25
#define KOUT 50
#define FW 1266
#define ROWS 64
#define THREADS 512
#define TOTALC 253
#define CK 4
#define NBUF 4
#define RSE 1272                         // fp16 elems per A row (2544B, 16B-aligned, LDSM conflict-free)
#define A_BYTES (ROWS * RSE * 2)         // 162816
#define KSB 3584                         // per-ks W block: 7 nt * 32 lanes * 16B
#define CHUNK_B (CK * KSB)               // 14336
#define WOFF A_BYTES
#define BIAS_OFF (WOFF + NBUF * CHUNK_B) // 220160
#define SMEM_TOTAL (BIAS_OFF + NLAYERS * KOUT * 4)   // 225160

// packed-linear W fragments: [gchunk(253)][ksl(4)][nt(7)][lane(32)][word(4)]
// word = {bhi_r0, bhi_r1, blo_r0, blo_r1} -> one LDS.128 per (ks, tile)
#define WFRAG_U32 (TOTALC * (CHUNK_B / 4))   // 906,752 words = 3.63 MB
__device__ uint32_t g_wfrag[WFRAG_U32];

__constant__ int CSTART[26] = {0,1,3,5,8,12,17,22,28,35,43,52,61,71,82,94,
                               106,119,133,148,164,180,197,215,234,253};

__device__ __forceinline__ uint32_t packh2(__half a, __half b) {
    return (uint32_t)__half_as_ushort(a) | ((uint32_t)__half_as_ushort(b) << 16);
}

// ---- prekernel: fp32 W -> fragment-ordered fp16 hi/lo quads, chunk-linear ----
__global__ void stage_w_kernel(const float* __restrict__ Ws) {
    int i = blockIdx.x * 256 + threadIdx.x;
    if (i >= WFRAG_U32) return;
    int gchunk = i / 3584, off = i % 3584;
    int layer = 0;
    while (layer < NLAYERS - 1 && CSTART[layer + 1] <= gchunk) layer++;
    int c = gchunk - CSTART[layer];
    int ksl = off / 896, o3 = off % 896;
    int nt = o3 / 128,  rem = o3 % 128;
    int ln = rem / 4,   word = rem % 4;
    int plane = word >> 1, reg = word & 1;
    int n = nt * 8 + (ln >> 2);
    int k = (c * CK + ksl) * 16 + ((ln & 3) << 1) + reg * 8;
    float w0 = 0.f, w1 = 0.f;
    if (n < KOUT && k + 1 < FW) {
        const float* p = Ws + ((size_t)layer * KOUT + n) * FW + k;
        w0 = p[0]; w1 = p[1];
    }
    uint32_t v;
    if (plane == 0) {
        v = packh2(__float2half_rn(w0), __float2half_rn(w1));
    } else {
        __half h0 = __float2half_rn(w0), h1 = __float2half_rn(w1);
        v = packh2(__float2half_rn(w0 - __half2float(h0)),
                   __float2half_rn(w1 - __half2float(h1)));
    }
    g_wfrag[i] = v;
}

#define MMA(d, a, b0_, b1_) \
    asm volatile("mma.sync.aligned.m16n8k16.row.col.f32.f16.f16.f32 " \
        "{%0,%1,%2,%3},{%4,%5,%6,%7},{%8,%9},{%0,%1,%2,%3};" \
        : "+f"(d[0]), "+f"(d[1]), "+f"(d[2]), "+f"(d[3]) \
        : "r"(a[0]), "r"(a[1]), "r"(a[2]), "r"(a[3]), "r"(b0_), "r"(b1_))

#define LDSM4(r, addr) \
    asm volatile("ldmatrix.sync.aligned.m8n8.x4.shared.b16 {%0,%1,%2,%3}, [%4];" \
        : "=r"(r[0]), "=r"(r[1]), "=r"(r[2]), "=r"(r[3]) : "r"(addr))

__device__ __forceinline__ void cp16(uint32_t dst, const void* src) {
    asm volatile("cp.async.cg.shared.global [%0], [%1], 16;" :: "r"(dst), "l"(src));
}

__global__ void __launch_bounds__(THREADS, 1) value_model_mma_kernel(
    const float* __restrict__ state,
    const float* __restrict__ bs,
    const float* __restrict__ Wout,
    const float* __restrict__ bout,
    float* __restrict__ out)
{
    extern __shared__ char smraw[];
    __half* A = (__half*)smraw;
    const uint32_t smb = (uint32_t)__cvta_generic_to_shared(smraw);
    float* biassm = (float*)(smraw + BIAS_OFF);

    const int tid  = threadIdx.x;
    const int lane = tid & 31;
    const int wid  = tid >> 5;
    const int cta  = blockIdx.x;
    const int mt   = wid & 3;     // which m16 tile (rows mt*16..mt*16+15)
    const int ng   = wid >> 2;    // n-tile pair: tiles ng*2, ng*2+1 (tile<7)

    // ---- zero A plane ----
    {
        uint4 z = make_uint4(0u, 0u, 0u, 0u);
        uint4* p = (uint4*)smraw;
        for (int i = tid; i < A_BYTES / 16; i += THREADS) p[i] = z;
    }
    // ---- biases to smem ----
    for (int i = tid; i < NLAYERS * KOUT; i += THREADS) biassm[i] = bs[i];
    __syncthreads();

    // ---- initial state (64 x 16) ----
    for (int idx = tid; idx < ROWS * 16; idx += THREADS) {
        int r = idx >> 4, j = idx & 15;
        A[r * RSE + j] = __float2half_rn(state[(cta * ROWS + r) * 16 + j]);
    }
    __syncthreads();

    // ldmatrix base: this warp's m16 tile
    const uint32_t abase = smb + (uint32_t)((mt * 16 + (lane & 15)) * RSE) * 2u
                               + (uint32_t)(lane >> 4) * 16u;

    // ---- prime the ring: stage chunks 0..2 ----
    #pragma unroll
    for (int s = 0; s < 3; s++) {
        const char* src = (const char*)g_wfrag + (size_t)s * CHUNK_B;
        uint32_t dst = smb + WOFF + (uint32_t)s * CHUNK_B;
        for (int i = tid; i < CHUNK_B / 16; i += THREADS)
            cp16(dst + i * 16, src + (size_t)i * 16);
        asm volatile("cp.async.commit_group;");
    }

    int gj = 0;
    int width = 16;
    for (int l = 0; l < NLAYERS; l++) {
        const int nks = (31 + 50 * l) >> 4;
        const int nch = CSTART[l + 1] - CSTART[l];

        float acc[2][4] = {};

        for (int c = 0; c < nch; c++) {
            asm volatile("cp.async.wait_group 2;" ::: "memory");  // chunk gj landed
            __syncthreads();                                      // publish + free (gj-1)'s buffer
            // stage chunk gj+3 into buffer (gj+3)%4 (== (gj-1)%4, freed by barrier above)
            {
                const int ch = gj + 3;
                if (ch < TOTALC) {
                    const char* src = (const char*)g_wfrag + (size_t)ch * CHUNK_B;
                    uint32_t dst = smb + WOFF + (uint32_t)(ch & 3) * CHUNK_B;
                    for (int i = tid; i < CHUNK_B / 16; i += THREADS)
                        cp16(dst + i * 16, src + (size_t)i * 16);
                }
                asm volatile("cp.async.commit_group;");           // always: keeps group count uniform
            }
            // compute chunk gj
            const char* wbuf = smraw + WOFF + (size_t)(gj & 3) * CHUNK_B;
            #pragma unroll
            for (int ksl = 0; ksl < CK; ksl++) {
                const int ks = c * CK + ksl;
                if (ks < nks) {
                    uint32_t a[4];
                    LDSM4(a, abase + (uint32_t)ks * 32u);
                    const uint4* bq = (const uint4*)(wbuf + ksl * KSB) + (ng * 64 + lane);
                    const uint4 b0 = bq[0];
                    MMA(acc[0], a, b0.x, b0.y);
                    MMA(acc[0], a, b0.z, b0.w);
                    if (ng < 3) {
                        const uint4 b1 = bq[32];
                        MMA(acc[1], a, b1.x, b1.y);
                        MMA(acc[1], a, b1.z, b1.w);
                    }
                }
            }
            gj++;
        }

        // padded-k tail cols overlap the epilogue write range -> fence readers first
        __syncthreads();

        // ---- epilogue: bias + leaky_relu, append to A (no reduction needed) ----
        #pragma unroll
        for (int t = 0; t < 2; t++) {
            const int tile = ng * 2 + t;
            if (tile < 7) {
                #pragma unroll
                for (int half = 0; half < 2; half++) {
                    const int n = tile * 8 + ((lane & 3) << 1) + half;
                    if (n < KOUT) {
                        const float bz = biassm[l * KOUT + n];
                        #pragma unroll
                        for (int rr = 0; rr < 2; rr++) {
                            float y = acc[t][rr * 2 + half] + bz;
                            y = (y > 0.f) ? y : 0.01f * y;
                            const int r = mt * 16 + (lane >> 2) + rr * 8;
                            A[r * RSE + width + n] = __float2half_rn(y);
                        }
                    }
                }
            }
        }
        width += KOUT;
        // no barrier here: next chunk's top barrier orders epilogue stores before reads
    }

    __syncthreads();

    // ---- final projection: out[r] = x . Wout + bout ----
    #pragma unroll
    for (int t = 0; t < 4; t++) {
        const int r = wid * 4 + t;
        float s = 0.f;
        for (int j = lane; j < FW; j += 32)
            s += __half2float(A[r * RSE + j]) * Wout[j];
        #pragma unroll
        for (int o = 16; o; o >>= 1) s += __shfl_xor_sync(0xffffffffu, s, o);
        if (lane == 0) out[cta * ROWS + r] = s + bout[0];
    }
}

extern "C" void kernel_launch(void* const* d_in, const int* in_sizes, int n_in,
                              void* d_out, int out_size) {
    const float* state = (const float*)d_in[0];
    const float* Ws    = (const float*)d_in[1];
    const float* bs    = (const float*)d_in[2];
    const float* Wout  = (const float*)d_in[3];
    const float* bout  = (const float*)d_in[4];
    float* out = (float*)d_out;

    const int B = in_sizes[0] / 16;   // 32768

    stage_w_kernel<<<(WFRAG_U32 + 255) / 256, 256>>>(Ws);

    cudaFuncSetAttribute(value_model_mma_kernel,
                         cudaFuncAttributeMaxDynamicSharedMemorySize, SMEM_TOTAL);
    value_model_mma_kernel<<<B / ROWS, THREADS, SMEM_TOTAL>>>(state, bs, Wout, bout, out);
}